// round 2
// baseline (speedup 1.0000x reference)
#include <cuda_runtime.h>
#include <cuda_bf16.h>

// ---------------- problem constants ----------------
#define G    3040
#define ATM  100
#define NTOK 43
#define FS   75
#define HS   128
#define H1S  128
#define NF   512
#define NH   256
#define DH   256

// ---------------- device scratch (static, allowed) ----------------
__device__ float d_xc [G * NF];        // [G,512]  concat(x, emb)
__device__ float d_t  [G * 512];       // t_pos | t_neg
__device__ float d_h  [G * 512];       // hp | hn
__device__ float d_t2 [G * 512];       // t2p | t2n
__device__ float d_z  [G * 512];       // zp | zn
__device__ float d_a1 [G * 256];
__device__ float d_a2 [G * 512];
__device__ float d_z3 [G * 256];
__device__ float d_zw [G * 256];
__device__ int   d_is64;

// ---------------- dtype sniff for encoded_drug ----------------
// If the buffer is int64 (little-endian), every odd 32-bit word is the high
// half of a token in [0,43) and is therefore 0. If it is int32, odd words are
// random tokens (P(all zero) ~ (1/43)^4096 ~ 0).
__global__ void sniff_kernel(const int* __restrict__ enc) {
    __shared__ int any;
    if (threadIdx.x == 0) any = 0;
    __syncthreads();
    int seen = 0;
    for (int i = threadIdx.x; i < 4096; i += 256)
        if (enc[2 * i + 1] != 0) seen = 1;
    if (seen) atomicOr(&any, 1);
    __syncthreads();
    if (threadIdx.x == 0) d_is64 = (any == 0) ? 1 : 0;
}

// ---------------- copy x into xc[:, 0:384] ----------------
__global__ void copyx_kernel(const float* __restrict__ x) {
    int i = blockIdx.x * 256 + threadIdx.x;
    if (i < G * 384) {
        int g = i / 384, c = i - g * 384;
        d_xc[g * NF + c] = x[i];
    }
}

// ---------------- molecular GCN: one block per graph ----------------
// smem layout (floats):
//   sAdj  [100][101]  = 10100   (adj^T, padded)
//   sW    [128*128]   = 16384   (Wm1 then Wm2; reduction scratch at the end)
//   bufA  [100*128]   = 12800   (P then XW2)
//   bufB  [100*128]   = 12800   (tok_emb copy then H1)
//   stok  100 ints
#define SM_ADJ  0
#define SM_W    10100
#define SM_BUFA 26484
#define SM_BUFB 39284
#define SM_TOK  52084
#define SM_FLOATS 52184          // 208,736 bytes

// Computes (for 16 warps, 32 lanes): Out[r][k] = sum_h Xs[r][h] * W[row(h)][k]
// where row(h) = tok[h] (if TOKW) else h. W rows are 128 floats.
// Each warp computes RPW rows x 128 cols (lane -> 4 consecutive cols).
template<int RPW, bool DOMAX, bool TOKW>
__device__ __forceinline__ void tile_mm(const float* __restrict__ Xs, int ldx,
                                        const float* __restrict__ Ws,
                                        const int* __restrict__ tok,
                                        int K, int Mrows,
                                        float* __restrict__ Out,
                                        float4& mx)
{
    const int lane = threadIdx.x & 31;
    const int warp = threadIdx.x >> 5;
    const int r0 = warp * RPW;

    int xoff[RPW];
#pragma unroll
    for (int i = 0; i < RPW; i++) {
        int rr = r0 + i;
        if (rr >= Mrows) rr = Mrows - 1;   // clamp (masked at store / harmless in max)
        xoff[i] = rr * ldx;
    }

    float acc[RPW][4];
#pragma unroll
    for (int i = 0; i < RPW; i++)
        acc[i][0] = acc[i][1] = acc[i][2] = acc[i][3] = 0.0f;

    const float* wbase = Ws + lane * 4;
#pragma unroll 4
    for (int h = 0; h < K; h++) {
        int wr = TOKW ? tok[h] : h;
        float4 wv = *(const float4*)(wbase + wr * 128);
#pragma unroll
        for (int i = 0; i < RPW; i++) {
            float xv = Xs[xoff[i] + h];
            acc[i][0] = fmaf(xv, wv.x, acc[i][0]);
            acc[i][1] = fmaf(xv, wv.y, acc[i][1]);
            acc[i][2] = fmaf(xv, wv.z, acc[i][2]);
            acc[i][3] = fmaf(xv, wv.w, acc[i][3]);
        }
    }

    if (DOMAX) {
#pragma unroll
        for (int i = 0; i < RPW; i++) {
            mx.x = fmaxf(mx.x, acc[i][0]);
            mx.y = fmaxf(mx.y, acc[i][1]);
            mx.z = fmaxf(mx.z, acc[i][2]);
            mx.w = fmaxf(mx.w, acc[i][3]);
        }
    } else {
#pragma unroll
        for (int i = 0; i < RPW; i++) {
            if (r0 + i < Mrows) {
                *(float4*)(Out + (r0 + i) * 128 + lane * 4) =
                    make_float4(acc[i][0], acc[i][1], acc[i][2], acc[i][3]);
            }
        }
    }
}

__global__ void __launch_bounds__(512, 1)
mol_kernel(const float* __restrict__ mol_adj,
           const void* __restrict__ encv,
           const float* __restrict__ tok_emb,
           const float* __restrict__ Wm1,
           const float* __restrict__ Wm2)
{
    extern __shared__ float sm[];
    float* sAdj = sm + SM_ADJ;
    float* sW   = sm + SM_W;
    float* bufA = sm + SM_BUFA;
    float* bufB = sm + SM_BUFB;
    int*   stok = (int*)(sm + SM_TOK);

    const int g = blockIdx.x;
    const int tid = threadIdx.x;
    const int is64 = d_is64;

    // tokens
    if (tid < ATM) {
        const int* e = (const int*)encv;
        stok[tid] = is64 ? e[2 * (g * ATM + tid)] : e[g * ATM + tid];
    }
    // adj^T (padded ld 101): sAdj[b][a] = mol_adj[g][a][b]
    for (int idx = tid; idx < ATM * ATM; idx += 512) {
        int a = idx / ATM, b = idx - a * ATM;
        sAdj[b * 101 + a] = mol_adj[g * (ATM * ATM) + idx];
    }
    // token embedding table -> bufB  [43][75]
    for (int idx = tid; idx < NTOK * FS; idx += 512) bufB[idx] = tok_emb[idx];
    // Wm1[g] -> sW  [75][128]
    for (int idx = tid; idx < FS * HS; idx += 512) sW[idx] = Wm1[g * (FS * HS) + idx];
    __syncthreads();

    float4 dummy = make_float4(0, 0, 0, 0);

    // Stage 1: P[43][128] = tok_emb @ Wm1[g]   (feats@Wm1 == P[tok])
    tile_mm<3, false, false>(bufB, FS, sW, nullptr, FS, NTOK, bufA, dummy);
    __syncthreads();

    // Stage 2: H1[100][128] = adj^T @ P[tok[a]]
    tile_mm<7, false, true>(sAdj, 101, bufA, stok, ATM, ATM, bufB, dummy);
    __syncthreads();

    // Wm2[g] -> sW  [128][128]
    for (int idx = tid; idx < HS * H1S; idx += 512) sW[idx] = Wm2[g * (HS * H1S) + idx];
    __syncthreads();

    // Stage 3: XW2[100][128] = H1 @ Wm2[g]
    tile_mm<7, false, false>(bufB, 128, sW, nullptr, HS, ATM, bufA, dummy);
    __syncthreads();

    // Stage 4: column-max over rows of adj^T @ XW2
    float4 mx = make_float4(-3.4e38f, -3.4e38f, -3.4e38f, -3.4e38f);
    tile_mm<7, true, false>(sAdj, 101, bufA, nullptr, ATM, ATM, nullptr, mx);
    __syncthreads();   // done with sW contents; reuse as reduction scratch

    const int lane = tid & 31, warp = tid >> 5;
    *(float4*)(sW + warp * 128 + lane * 4) = mx;
    __syncthreads();
    if (tid < 128) {
        float m = sW[tid];
#pragma unroll
        for (int w = 1; w < 16; w++) m = fmaxf(m, sW[w * 128 + tid]);
        d_xc[g * NF + 384 + tid] = m;   // write emb directly into concat slot
    }
}

// ---------------- generic fp32 tiled GEMM (64x64x16, 4x4 microtile) ----------
struct GemmP {
    const float* A; const float* B; float* C;
    int M, N, K, lda, ldb, ldc, relu, transB;
};

__global__ void __launch_bounds__(256)
sgemm(GemmP P0, GemmP P1)
{
    GemmP p = (blockIdx.z == 0) ? P0 : P1;
    __shared__ float As[16 * 68];
    __shared__ float Bs[16 * 68];

    const int t = threadIdx.x;
    const int tx = t & 15, ty = t >> 4;
    const int m0 = blockIdx.y * 64, n0 = blockIdx.x * 64;

    float acc[4][4];
#pragma unroll
    for (int i = 0; i < 4; i++)
#pragma unroll
        for (int j = 0; j < 4; j++) acc[i][j] = 0.0f;

    for (int k0 = 0; k0 < p.K; k0 += 16) {
        // A tile: As[k][m] (transposed store)
#pragma unroll
        for (int i = 0; i < 4; i++) {
            int e = t + 256 * i;
            int r = e >> 4, c = e & 15;
            int gr = m0 + r; if (gr >= p.M) gr = p.M - 1;
            As[c * 68 + r] = p.A[gr * p.lda + k0 + c];
        }
        if (!p.transB) {
            // B tile: Bs[k][n]
            int r = t >> 4; int cb = (t & 15) * 4;
#pragma unroll
            for (int j = 0; j < 4; j++) {
                int gc = n0 + cb + j; if (gc >= p.N) gc = p.N - 1;
                Bs[r * 68 + cb + j] = p.B[(k0 + r) * p.ldb + gc];
            }
        } else {
            // B stored [N][K]; want Bs[k][n]
#pragma unroll
            for (int i = 0; i < 4; i++) {
                int e = t + 256 * i;
                int r = e >> 4, c = e & 15;           // r = n idx, c = k idx
                int gn = n0 + r; if (gn >= p.N) gn = p.N - 1;
                Bs[c * 68 + r] = p.B[gn * p.ldb + k0 + c];
            }
        }
        __syncthreads();

#pragma unroll
        for (int kk = 0; kk < 16; kk++) {
            float4 av = *(const float4*)&As[kk * 68 + ty * 4];
            float4 bv = *(const float4*)&Bs[kk * 68 + tx * 4];
            float aa[4] = {av.x, av.y, av.z, av.w};
            float bb[4] = {bv.x, bv.y, bv.z, bv.w};
#pragma unroll
            for (int i = 0; i < 4; i++)
#pragma unroll
                for (int j = 0; j < 4; j++)
                    acc[i][j] = fmaf(aa[i], bb[j], acc[i][j]);
        }
        __syncthreads();
    }

#pragma unroll
    for (int i = 0; i < 4; i++) {
        int r = m0 + ty * 4 + i;
        if (r < p.M) {
#pragma unroll
            for (int j = 0; j < 4; j++) {
                int c = n0 + tx * 4 + j;
                if (c < p.N) {
                    float v = acc[i][j];
                    if (p.relu) v = fmaxf(v, 0.0f);
                    p.C[r * p.ldc + c] = v;
                }
            }
        }
    }
}

// ---------------- host launcher ----------------
static GemmP mk(const float* A, int lda, const float* B, int ldb,
                float* C, int ldc, int M, int N, int K, int relu, int tb)
{
    GemmP p; p.A = A; p.B = B; p.C = C; p.M = M; p.N = N; p.K = K;
    p.lda = lda; p.ldb = ldb; p.ldc = ldc; p.relu = relu; p.transB = tb;
    return p;
}

static void launch_gemm(const GemmP& p0, const GemmP& p1, int nz)
{
    dim3 grid((p0.N + 63) / 64, (p0.M + 63) / 64, nz);
    sgemm<<<grid, 256>>>(p0, p1);
}

extern "C" void kernel_launch(void* const* d_in, const int* in_sizes, int n_in,
                              void* d_out, int out_size)
{
    const float* x       = (const float*)d_in[0];
    const float* adj_pos = (const float*)d_in[1];
    const float* adj_neg = (const float*)d_in[2];
    const float* mol_adj = (const float*)d_in[3];
    const void*  enc     = d_in[4];
    const float* tok_emb = (const float*)d_in[5];
    const float* Wm1     = (const float*)d_in[6];
    const float* Wm2     = (const float*)d_in[7];
    const float* Wp1     = (const float*)d_in[8];
    const float* Wp2     = (const float*)d_in[9];
    const float* Wn1     = (const float*)d_in[10];
    const float* Wn2     = (const float*)d_in[11];
    const float* Wd1     = (const float*)d_in[12];
    const float* Wd2     = (const float*)d_in[13];
    const float* Wd3     = (const float*)d_in[14];
    const float* Wdec    = (const float*)d_in[15];
    float* out = (float*)d_out;

    (void)in_sizes; (void)n_in; (void)out_size;

    cudaFuncSetAttribute(mol_kernel, cudaFuncAttributeMaxDynamicSharedMemorySize,
                         SM_FLOATS * sizeof(float));

    float *xc, *t, *h, *t2, *z, *a1, *a2, *z3, *zw;
    cudaGetSymbolAddress((void**)&xc, d_xc);
    cudaGetSymbolAddress((void**)&t,  d_t);
    cudaGetSymbolAddress((void**)&h,  d_h);
    cudaGetSymbolAddress((void**)&t2, d_t2);
    cudaGetSymbolAddress((void**)&z,  d_z);
    cudaGetSymbolAddress((void**)&a1, d_a1);
    cudaGetSymbolAddress((void**)&a2, d_a2);
    cudaGetSymbolAddress((void**)&z3, d_z3);
    cudaGetSymbolAddress((void**)&zw, d_zw);

    // 1) dtype sniff for encoded_drug
    sniff_kernel<<<1, 256>>>((const int*)enc);
    // 2) xc[:, :384] = x
    copyx_kernel<<<(G * 384 + 255) / 256, 256>>>(x);
    // 3) molecular GCN -> xc[:, 384:512]
    mol_kernel<<<G, 512, SM_FLOATS * sizeof(float)>>>(mol_adj, enc, tok_emb, Wm1, Wm2);

    // 4) t = xc @ [Wp1 | Wn1]
    launch_gemm(mk(xc, NF, Wp1, NH, t,       512, G, NH, NF, 0, 0),
                mk(xc, NF, Wn1, NH, t + 256, 512, G, NH, NF, 0, 0), 2);
    // 5) h = relu(adj @ t)
    launch_gemm(mk(adj_pos, G, t,       512, h,       512, G, NH, G, 1, 0),
                mk(adj_neg, G, t + 256, 512, h + 256, 512, G, NH, G, 1, 0), 2);
    // 6) t2 = h @ [Wp2 | Wn2]
    launch_gemm(mk(h,       512, Wp2, NH, t2,       512, G, NH, NH, 0, 0),
                mk(h + 256, 512, Wn2, NH, t2 + 256, 512, G, NH, NH, 0, 0), 2);
    // 7) z = adj @ t2   (zp | zn concat)
    launch_gemm(mk(adj_pos, G, t2,       512, z,       512, G, NH, G, 0, 0),
                mk(adj_neg, G, t2 + 256, 512, z + 256, 512, G, NH, G, 0, 0), 2);

    // 8) a1 = relu(z @ Wd1)
    GemmP p8 = mk(z, 512, Wd1, DH, a1, 256, G, DH, 2 * NH, 1, 0);
    launch_gemm(p8, p8, 1);
    // 9) a2 = relu(a1 @ Wd2)
    GemmP p9 = mk(a1, 256, Wd2, 2 * DH, a2, 512, G, 2 * DH, DH, 1, 0);
    launch_gemm(p9, p9, 1);
    // 10) z3 = a2 @ Wd3
    GemmP p10 = mk(a2, 512, Wd3, DH, z3, 256, G, DH, 2 * DH, 0, 0);
    launch_gemm(p10, p10, 1);
    // 11) zw = z3 @ Wdec
    GemmP p11 = mk(z3, 256, Wdec, DH, zw, 256, G, DH, DH, 0, 0);
    launch_gemm(p11, p11, 1);
    // 12) out = zw @ z3^T
    GemmP p12 = mk(zw, 256, z3, 256, out, G, G, G, DH, 0, 1);
    launch_gemm(p12, p12, 1);
}

// round 5
// speedup vs baseline: 1.7335x; 1.7335x over previous
#include <cuda_runtime.h>
#include <cuda_bf16.h>

// ---------------- problem constants ----------------
#define G    3040
#define ATM  100
#define NTOK 43
#define FS   75
#define HS   128
#define H1S  128
#define NF   512
#define NH   256
#define DH   256

// ---------------- device scratch (static, allowed) ----------------
__device__ float d_xc  [G * NF];        // [G,512]  concat(x, emb)
__device__ float d_t   [G * 512];       // t_pos | t_neg
__device__ float d_h   [G * 512];       // hp | hn
__device__ float d_t2  [G * 512];       // t2p | t2n
__device__ float d_z   [G * 512];       // zp | zn
__device__ float d_a1  [G * 256];
__device__ float d_a2  [G * 512];
__device__ float d_z3  [G * 256];
__device__ float d_zw  [G * 256];
__device__ float d_part[3 * G * 512];   // split-K partials
__device__ int   d_is64;

// ---------------- dtype sniff for encoded_drug ----------------
__global__ void sniff_kernel(const int* __restrict__ enc) {
    __shared__ int any;
    if (threadIdx.x == 0) any = 0;
    __syncthreads();
    int seen = 0;
    for (int i = threadIdx.x; i < 4096; i += 256)
        if (enc[2 * i + 1] != 0) seen = 1;
    if (seen) atomicOr(&any, 1);
    __syncthreads();
    if (threadIdx.x == 0) d_is64 = (any == 0) ? 1 : 0;
}

// ---------------- copy x into xc[:, 0:384] ----------------
__global__ void copyx_kernel(const float* __restrict__ x) {
    int i = blockIdx.x * 256 + threadIdx.x;
    if (i < G * 384) {
        int g = i / 384, c = i - g * 384;
        d_xc[g * NF + c] = x[i];
    }
}

// ---------------- split-K reduce (+optional relu) ----------------
__global__ void reduce_kernel(float* __restrict__ out, int n, int relu) {
    int i = blockIdx.x * 256 + threadIdx.x;
    if (i < n) {
        float v = d_part[i] + d_part[i + n] + d_part[i + 2 * n];
        out[i] = relu ? fmaxf(v, 0.0f) : v;
    }
}

// ---------------- molecular GCN: one block per graph ----------------
// Algebra: feats = S @ E  (S = one-hot token select, E = tok_emb)
//   P = E @ Wm1                [43,128]
//   Q = P @ Wm2                [43,128]
//   C = adjT @ S               [100,43]  (scatter-add)
//   D = adjT @ C               [100,43]
//   emb = colmax_rows(D @ Q)   [128]
// smem layout (floats):
#define SM_ADJ  0        // [100][101]            10100
#define SM_W    10100    // 128*128               16384
#define SM_P    26484    // 43*128                 5504
#define SM_Q    31988    // 43*128                 5504
#define SM_E    37492    // 43*75 (pad 3228)       3228
#define SM_C    40720    // [100][64]              6400
#define SM_D    47120    // [100][64]              6400
#define SM_TOK  53520    // 100 ints
#define SM_FLOATS 53624  // 214,496 bytes

// Out[r][k] = sum_h Xs[r][h] * W[h][k], W rows are 128 floats wide.
// 16 warps; warp w computes rows w*RPW..; lane covers 4 consecutive cols.
template<int RPW, bool DOMAX>
__device__ __forceinline__ void tile_mm(const float* __restrict__ Xs, int ldx,
                                        const float* __restrict__ Ws,
                                        int K, int Mrows,
                                        float* __restrict__ Out,
                                        float4& mx)
{
    const int lane = threadIdx.x & 31;
    const int warp = threadIdx.x >> 5;
    const int r0 = warp * RPW;

    int xoff[RPW];
#pragma unroll
    for (int i = 0; i < RPW; i++) {
        int rr = r0 + i;
        if (rr >= Mrows) rr = Mrows - 1;
        xoff[i] = rr * ldx;
    }

    float acc[RPW][4];
#pragma unroll
    for (int i = 0; i < RPW; i++)
        acc[i][0] = acc[i][1] = acc[i][2] = acc[i][3] = 0.0f;

    const float* wbase = Ws + lane * 4;
#pragma unroll 4
    for (int h = 0; h < K; h++) {
        float4 wv = *(const float4*)(wbase + h * 128);
#pragma unroll
        for (int i = 0; i < RPW; i++) {
            float xv = Xs[xoff[i] + h];
            acc[i][0] = fmaf(xv, wv.x, acc[i][0]);
            acc[i][1] = fmaf(xv, wv.y, acc[i][1]);
            acc[i][2] = fmaf(xv, wv.z, acc[i][2]);
            acc[i][3] = fmaf(xv, wv.w, acc[i][3]);
        }
    }

    if (DOMAX) {
#pragma unroll
        for (int i = 0; i < RPW; i++) {
            mx.x = fmaxf(mx.x, acc[i][0]);
            mx.y = fmaxf(mx.y, acc[i][1]);
            mx.z = fmaxf(mx.z, acc[i][2]);
            mx.w = fmaxf(mx.w, acc[i][3]);
        }
    } else {
#pragma unroll
        for (int i = 0; i < RPW; i++) {
            if (r0 + i < Mrows) {
                *(float4*)(Out + (r0 + i) * 128 + lane * 4) =
                    make_float4(acc[i][0], acc[i][1], acc[i][2], acc[i][3]);
            }
        }
    }
}

__global__ void __launch_bounds__(512, 1)
mol_kernel(const float* __restrict__ mol_adj,
           const void* __restrict__ encv,
           const float* __restrict__ tok_emb,
           const float* __restrict__ Wm1,
           const float* __restrict__ Wm2)
{
    extern __shared__ float sm[];
    float* sAdj = sm + SM_ADJ;
    float* sW   = sm + SM_W;
    float* sP   = sm + SM_P;
    float* sQ   = sm + SM_Q;
    float* sE   = sm + SM_E;
    float* sC   = sm + SM_C;
    float* sD   = sm + SM_D;
    int*   stok = (int*)(sm + SM_TOK);

    const int g = blockIdx.x;
    const int tid = threadIdx.x;
    const int lane = tid & 31, warp = tid >> 5;
    const int is64 = d_is64;

    // ---- stage 0: loads ----
    if (tid < ATM) {
        const int* e = (const int*)encv;
        stok[tid] = is64 ? e[2 * (g * ATM + tid)] : e[g * ATM + tid];
    }
    for (int idx = tid; idx < ATM * ATM; idx += 512) {
        int a = idx / ATM, b = idx - a * ATM;
        sAdj[b * 101 + a] = mol_adj[g * (ATM * ATM) + idx];   // adj^T
    }
    for (int idx = tid; idx < NTOK * FS; idx += 512) sE[idx] = tok_emb[idx];
    for (int idx = tid; idx < FS * HS; idx += 512) sW[idx] = Wm1[g * (FS * HS) + idx];
    for (int idx = tid; idx < ATM * 64; idx += 512) sC[idx] = 0.0f;
    __syncthreads();

    // ---- stage 1: C = adjT @ S (scatter-add), 400 threads ----
    if (tid < 400) {
        int b = tid >> 2, q = tid & 3;
        const float* arow = sAdj + b * 101;
        float* crow = sC + b * 64;
        for (int a = q * 25; a < q * 25 + 25; a++)
            atomicAdd(&crow[stok[a]], arow[a]);
    }
    __syncthreads();

    float4 dummy = make_float4(0, 0, 0, 0);

    // ---- stage 2: P = E @ Wm1 ----
    tile_mm<3, false>(sE, FS, sW, FS, NTOK, sP, dummy);
    __syncthreads();

    // ---- stage 3: Wm2 -> sW ----
    for (int idx = tid; idx < HS * H1S; idx += 512) sW[idx] = Wm2[g * (HS * H1S) + idx];
    __syncthreads();

    // ---- stage 4: Q = P @ Wm2 ----
    tile_mm<3, false>(sP, 128, sW, HS, NTOK, sQ, dummy);
    __syncthreads();

    // ---- stage 5: D = adjT @ C  (rows: 16 warps x 7; cols: lane, lane+32) ----
    {
        const int r0 = warp * 7;
        float ac0[7], ac1[7];
#pragma unroll
        for (int i = 0; i < 7; i++) { ac0[i] = 0.0f; ac1[i] = 0.0f; }
        int roff[7];
#pragma unroll
        for (int i = 0; i < 7; i++) {
            int rr = r0 + i; if (rr >= ATM) rr = ATM - 1;
            roff[i] = rr * 101;
        }
        for (int a = 0; a < ATM; a++) {
            float c0 = sC[a * 64 + lane];
            float c1 = sC[a * 64 + 32 + lane];
#pragma unroll
            for (int i = 0; i < 7; i++) {
                float av = sAdj[roff[i] + a];
                ac0[i] = fmaf(av, c0, ac0[i]);
                ac1[i] = fmaf(av, c1, ac1[i]);
            }
        }
#pragma unroll
        for (int i = 0; i < 7; i++) {
            if (r0 + i < ATM) {
                sD[(r0 + i) * 64 + lane] = ac0[i];
                sD[(r0 + i) * 64 + 32 + lane] = ac1[i];
            }
        }
    }
    __syncthreads();

    // ---- stage 6: emb = colmax(D @ Q) ----
    float4 mx = make_float4(-3.4e38f, -3.4e38f, -3.4e38f, -3.4e38f);
    tile_mm<7, true>(sD, 64, sQ, NTOK, ATM, nullptr, mx);
    __syncthreads();       // sW free, reuse as reduction scratch

    *(float4*)(sW + warp * 128 + lane * 4) = mx;
    __syncthreads();
    if (tid < 128) {
        float m = sW[tid];
#pragma unroll
        for (int w = 1; w < 16; w++) m = fmaxf(m, sW[w * 128 + tid]);
        d_xc[g * NF + 384 + tid] = m;
    }
}

// ---------------- fp32 GEMM: 128x128 tile, 8x8 microtile, split-K ----------
struct GemmP {
    const float* A; const float* B; float* C;
    int M, N, K, lda, ldb, ldc;
    int relu, transB, kspl, Kc;
    long long pstride;
};

__global__ void __launch_bounds__(256, 2)
sgemm2(GemmP P0, GemmP P1)
{
    __shared__ float As[8 * 132];
    __shared__ float Bs[8 * 132];

    const int z = blockIdx.z;
    GemmP p = (z / P0.kspl) ? P1 : P0;
    const int slice = z % p.kspl;
    const int k0 = slice * p.Kc;
    const int kend = min(p.K, k0 + p.Kc);
    float* Cp = p.C + (long long)slice * p.pstride;

    const int t = threadIdx.x;
    const int tx = t & 15, ty = t >> 4;
    const int m0 = blockIdx.y * 128, n0 = blockIdx.x * 128;

    // A staging map: thread -> (row, k-quad)
    const int ami = t >> 1;
    const int akq = (t & 1) * 4;
    const int agr = min(m0 + ami, p.M - 1);
    const float* Aptr = p.A + (long long)agr * p.lda + akq;

    // B staging map
    const float* Bptr;
    int bni = 0, bkq = 0, bri = 0, bnq = 0;
    if (p.transB) {
        bni = t >> 1; bkq = (t & 1) * 4;
        int gn = min(n0 + bni, p.N - 1);
        Bptr = p.B + (long long)gn * p.ldb + bkq;
    } else {
        bri = t >> 5; bnq = (t & 31) * 4;
        int gn = min(n0 + bnq, p.N - 4);
        Bptr = p.B + (long long)bri * p.ldb + gn;
    }

    float acc[8][8];
#pragma unroll
    for (int i = 0; i < 8; i++)
#pragma unroll
        for (int j = 0; j < 8; j++) acc[i][j] = 0.0f;

    float4 ra = *(const float4*)(Aptr + k0);
    float4 rb = p.transB ? *(const float4*)(Bptr + k0)
                         : *(const float4*)(Bptr + (long long)k0 * p.ldb);

    for (int kb = k0; kb < kend; kb += 8) {
        As[(akq + 0) * 132 + ami] = ra.x;
        As[(akq + 1) * 132 + ami] = ra.y;
        As[(akq + 2) * 132 + ami] = ra.z;
        As[(akq + 3) * 132 + ami] = ra.w;
        if (p.transB) {
            Bs[(bkq + 0) * 132 + bni] = rb.x;
            Bs[(bkq + 1) * 132 + bni] = rb.y;
            Bs[(bkq + 2) * 132 + bni] = rb.z;
            Bs[(bkq + 3) * 132 + bni] = rb.w;
        } else {
            *(float4*)&Bs[bri * 132 + bnq] = rb;
        }
        __syncthreads();

        int kn = kb + 8;
        if (kn < kend) {
            ra = *(const float4*)(Aptr + kn);
            rb = p.transB ? *(const float4*)(Bptr + kn)
                          : *(const float4*)(Bptr + (long long)kn * p.ldb);
        }

#pragma unroll
        for (int kk = 0; kk < 8; kk++) {
            float4 a0 = *(const float4*)&As[kk * 132 + ty * 8];
            float4 a1 = *(const float4*)&As[kk * 132 + ty * 8 + 4];
            float4 b0 = *(const float4*)&Bs[kk * 132 + tx * 8];
            float4 b1 = *(const float4*)&Bs[kk * 132 + tx * 8 + 4];
            float av[8] = {a0.x, a0.y, a0.z, a0.w, a1.x, a1.y, a1.z, a1.w};
            float bv[8] = {b0.x, b0.y, b0.z, b0.w, b1.x, b1.y, b1.z, b1.w};
#pragma unroll
            for (int i = 0; i < 8; i++)
#pragma unroll
                for (int j = 0; j < 8; j++)
                    acc[i][j] = fmaf(av[i], bv[j], acc[i][j]);
        }
        __syncthreads();
    }

#pragma unroll
    for (int i = 0; i < 8; i++) {
        int r = m0 + ty * 8 + i;
        if (r < p.M) {
#pragma unroll
            for (int j = 0; j < 8; j++) {
                int c = n0 + tx * 8 + j;
                if (c < p.N) {
                    float v = acc[i][j];
                    if (p.relu) v = fmaxf(v, 0.0f);
                    Cp[(long long)r * p.ldc + c] = v;
                }
            }
        }
    }
}

// ---------------- host launcher ----------------
static GemmP mk2(const float* A, int lda, const float* B, int ldb,
                 float* C, int ldc, int M, int N, int K,
                 int relu, int tb, int kspl, int Kc, long long pstride)
{
    GemmP p; p.A = A; p.B = B; p.C = C; p.M = M; p.N = N; p.K = K;
    p.lda = lda; p.ldb = ldb; p.ldc = ldc; p.relu = relu; p.transB = tb;
    p.kspl = kspl; p.Kc = Kc; p.pstride = pstride;
    return p;
}

static void launch2(const GemmP& p0, const GemmP& p1, int nbranch)
{
    dim3 grid((p0.N + 127) / 128, (p0.M + 127) / 128, nbranch * p0.kspl);
    sgemm2<<<grid, 256>>>(p0, p1);
}

extern "C" void kernel_launch(void* const* d_in, const int* in_sizes, int n_in,
                              void* d_out, int out_size)
{
    const float* x       = (const float*)d_in[0];
    const float* adj_pos = (const float*)d_in[1];
    const float* adj_neg = (const float*)d_in[2];
    const float* mol_adj = (const float*)d_in[3];
    const void*  enc     = d_in[4];
    const float* tok_emb = (const float*)d_in[5];
    const float* Wm1     = (const float*)d_in[6];
    const float* Wm2     = (const float*)d_in[7];
    const float* Wp1     = (const float*)d_in[8];
    const float* Wp2     = (const float*)d_in[9];
    const float* Wn1     = (const float*)d_in[10];
    const float* Wn2     = (const float*)d_in[11];
    const float* Wd1     = (const float*)d_in[12];
    const float* Wd2     = (const float*)d_in[13];
    const float* Wd3     = (const float*)d_in[14];
    const float* Wdec    = (const float*)d_in[15];
    float* out = (float*)d_out;

    (void)in_sizes; (void)n_in; (void)out_size;

    cudaFuncSetAttribute(mol_kernel, cudaFuncAttributeMaxDynamicSharedMemorySize,
                         SM_FLOATS * sizeof(float));

    float *xc, *t, *h, *t2, *zb, *a1, *a2, *z3, *zw, *part;
    cudaGetSymbolAddress((void**)&xc,   d_xc);
    cudaGetSymbolAddress((void**)&t,    d_t);
    cudaGetSymbolAddress((void**)&h,    d_h);
    cudaGetSymbolAddress((void**)&t2,   d_t2);
    cudaGetSymbolAddress((void**)&zb,   d_z);
    cudaGetSymbolAddress((void**)&a1,   d_a1);
    cudaGetSymbolAddress((void**)&a2,   d_a2);
    cudaGetSymbolAddress((void**)&z3,   d_z3);
    cudaGetSymbolAddress((void**)&zw,   d_zw);
    cudaGetSymbolAddress((void**)&part, d_part);

    const int NE = G * 512;

    // 1) dtype sniff
    sniff_kernel<<<1, 256>>>((const int*)enc);
    // 2) xc[:, :384] = x
    copyx_kernel<<<(G * 384 + 255) / 256, 256>>>(x);
    // 3) molecular GCN -> xc[:, 384:512]
    mol_kernel<<<G, 512, SM_FLOATS * sizeof(float)>>>(mol_adj, enc, tok_emb, Wm1, Wm2);

    // 4) t = xc @ [Wp1 | Wn1]
    launch2(mk2(xc, NF, Wp1, NH, t,       512, G, NH, NF, 0, 0, 1, NF, 0),
            mk2(xc, NF, Wn1, NH, t + 256, 512, G, NH, NF, 0, 0, 1, NF, 0), 2);

    // 5) h = relu(adj @ t)    (split-K=3, Kc=1016)
    launch2(mk2(adj_pos, G, t,       512, part,       512, G, NH, G, 0, 0, 3, 1016, NE),
            mk2(adj_neg, G, t + 256, 512, part + 256, 512, G, NH, G, 0, 0, 3, 1016, NE), 2);
    reduce_kernel<<<(NE + 255) / 256, 256>>>(h, NE, 1);

    // 6) t2 = h @ [Wp2 | Wn2]
    launch2(mk2(h,       512, Wp2, NH, t2,       512, G, NH, NH, 0, 0, 1, NH, 0),
            mk2(h + 256, 512, Wn2, NH, t2 + 256, 512, G, NH, NH, 0, 0, 1, NH, 0), 2);

    // 7) z = adj @ t2
    launch2(mk2(adj_pos, G, t2,       512, part,       512, G, NH, G, 0, 0, 3, 1016, NE),
            mk2(adj_neg, G, t2 + 256, 512, part + 256, 512, G, NH, G, 0, 0, 3, 1016, NE), 2);
    reduce_kernel<<<(NE + 255) / 256, 256>>>(zb, NE, 0);

    // 8) a1 = relu(z @ Wd1)
    {
        GemmP p = mk2(zb, 512, Wd1, DH, a1, 256, G, DH, 2 * NH, 1, 0, 1, 2 * NH, 0);
        launch2(p, p, 1);
    }
    // 9) a2 = relu(a1 @ Wd2)
    {
        GemmP p = mk2(a1, 256, Wd2, 2 * DH, a2, 512, G, 2 * DH, DH, 1, 0, 1, DH, 0);
        launch2(p, p, 1);
    }
    // 10) z3 = a2 @ Wd3
    {
        GemmP p = mk2(a2, 512, Wd3, DH, z3, 256, G, DH, 2 * DH, 0, 0, 1, 2 * DH, 0);
        launch2(p, p, 1);
    }
    // 11) zw = z3 @ Wdec
    {
        GemmP p = mk2(z3, 256, Wdec, DH, zw, 256, G, DH, DH, 0, 0, 1, DH, 0);
        launch2(p, p, 1);
    }
    // 12) out = zw @ z3^T
    {
        GemmP p = mk2(zw, 256, z3, 256, out, G, G, G, DH, 0, 1, 1, DH, 0);
        launch2(p, p, 1);
    }
}